// round 7
// baseline (speedup 1.0000x reference)
#include <cuda_runtime.h>
#include <cuda_bf16.h>
#include <cstdint>

#define LSEQ 2048
typedef unsigned long long ull;

__device__ float g_IZ[32 * LSEQ];
__device__ float g_ctx_scratch[2 * 16 * 2048 * 64];

// ---- smem byte offsets for score kernel (pitch 72 bf16 = 144B rows) ----
#define OQH 0
#define OQL 18432
#define OKH 36864
#define OKL 55296
#define OEH 73728
#define OEL 101376
#define ORS 129024
#define RSP 196
#define SMEM_TOT (229376)

__device__ __forceinline__ uint32_t smem_u32(const void* p) {
    uint32_t a;
    asm("{ .reg .u64 t; cvta.to.shared.u64 t, %1; cvt.u32.u64 %0, t; }" : "=r"(a) : "l"(p));
    return a;
}
__device__ __forceinline__ void ldmA(uint32_t* a, uint32_t addr) {
    asm volatile("ldmatrix.sync.aligned.m8n8.x4.shared.b16 {%0,%1,%2,%3}, [%4];"
        : "=r"(a[0]), "=r"(a[1]), "=r"(a[2]), "=r"(a[3]) : "r"(addr));
}
__device__ __forceinline__ void ldmB(uint32_t* b, uint32_t addr) {
    asm volatile("ldmatrix.sync.aligned.m8n8.x2.shared.b16 {%0,%1}, [%2];"
        : "=r"(b[0]), "=r"(b[1]) : "r"(addr));
}
__device__ __forceinline__ void ldmBT(uint32_t* b, uint32_t addr) {
    asm volatile("ldmatrix.sync.aligned.m8n8.x2.trans.shared.b16 {%0,%1}, [%2];"
        : "=r"(b[0]), "=r"(b[1]) : "r"(addr));
}
__device__ __forceinline__ void mmabf(float* d, const uint32_t* a, const uint32_t* b) {
    asm volatile("mma.sync.aligned.m16n8k16.row.col.f32.bf16.bf16.f32 "
        "{%0,%1,%2,%3}, {%4,%5,%6,%7}, {%8,%9}, {%0,%1,%2,%3};"
        : "+f"(d[0]), "+f"(d[1]), "+f"(d[2]), "+f"(d[3])
        : "r"(a[0]), "r"(a[1]), "r"(a[2]), "r"(a[3]), "r"(b[0]), "r"(b[1]));
}
__device__ __forceinline__ uint32_t pkbf(float a, float b) {
    __nv_bfloat162 h = __floats2bfloat162_rn(a, b);
    return *(uint32_t*)&h;
}
__device__ __forceinline__ void split72(char* hi, char* lo, int r, int c4, float4 v) {
    float hx = __bfloat162float(__float2bfloat16(v.x));
    float hy = __bfloat162float(__float2bfloat16(v.y));
    float hz = __bfloat162float(__float2bfloat16(v.z));
    float hw = __bfloat162float(__float2bfloat16(v.w));
    int off = r * 144 + c4 * 8;
    *(uint2*)(hi + off) = make_uint2(pkbf(v.x, v.y), pkbf(v.z, v.w));
    *(uint2*)(lo + off) = make_uint2(pkbf(v.x - hx, v.y - hy), pkbf(v.z - hz, v.w - hw));
}
__device__ __forceinline__ void split136(char* hi, char* lo, int r, int c4, float4 v) {
    float hx = __bfloat162float(__float2bfloat16(v.x));
    float hy = __bfloat162float(__float2bfloat16(v.y));
    float hz = __bfloat162float(__float2bfloat16(v.z));
    float hw = __bfloat162float(__float2bfloat16(v.w));
    int off = r * 272 + c4 * 8;
    *(uint2*)(hi + off) = make_uint2(pkbf(v.x, v.y), pkbf(v.z, v.w));
    *(uint2*)(lo + off) = make_uint2(pkbf(v.x - hx, v.y - hy), pkbf(v.z - hz, v.w - hw));
}

// ================= Kernel A: mma.sync scores -> unnormalized exp + 1/z =====
__global__ void __launch_bounds__(256, 1)
score_mma(const float* __restrict__ Q, const float* __restrict__ K,
          const float* __restrict__ Er, float* __restrict__ attn)
{
    extern __shared__ char sm[];
    const uint32_t sb = smem_u32(sm);
    float* Rs = (float*)(sm + ORS);

    const int qt = 15 - (int)blockIdx.x;
    const int bh = blockIdx.y;
    const int q0 = qt * 128;
    const int t = threadIdx.x;
    const int wid = t >> 5, lane = t & 31;
    const int wm = wid >> 1, wn = wid & 1;

    const float* Qg = Q + (size_t)bh * LSEQ * 64;
    const float* Kg = K + (size_t)bh * LSEQ * 64;
    float* attng = attn + (size_t)bh * LSEQ * LSEQ;

    for (int i = t; i < 2048; i += 256) {
        int r = i >> 4, c4 = i & 15;
        split72(sm + OQH, sm + OQL, r, c4,
                *((const float4*)(Qg + (size_t)(q0 + r) * 64 + 4 * c4)));
    }
    __syncthreads();

    const int arow = (lane & 7) + 8 * ((lane >> 3) & 1);
    const int acolB = 16 * (lane >> 4);
    uint32_t AH[2][4][4], AL[2][4][4];
#pragma unroll
    for (int mt = 0; mt < 2; mt++)
#pragma unroll
        for (int ks = 0; ks < 4; ks++) {
            uint32_t ro = (uint32_t)((32 * wm + 16 * mt + arow) * 144 + ks * 32 + acolB);
            ldmA(AH[mt][ks], sb + OQH + ro);
            ldmA(AL[mt][ks], sb + OQL + ro);
        }

    const int browB = (lane & 7) * 144;
    const int bcolB = 16 * ((lane >> 3) & 1);
    float zacc[2][2] = {{0.f, 0.f}, {0.f, 0.f}};

    for (int kt = 0; kt <= qt; kt++) {
        const int k0 = kt * 128;
        __syncthreads();
        for (int i = t; i < 2048; i += 256) {
            int r = i >> 4, c4 = i & 15;
            split72(sm + OKH, sm + OKL, r, c4,
                    *((const float4*)(Kg + (size_t)(k0 + r) * 64 + 4 * c4)));
        }
#pragma unroll 1
        for (int kh = 0; kh < 2; kh++) {
            const int vlo = q0 - k0 - 64 * kh - 63;
            for (int i = t; i < 3072; i += 256) {
                int j = i >> 4, c4 = i & 15;
                int e = 2047 - (vlo + j);
                float4 v = make_float4(0.f, 0.f, 0.f, 0.f);
                if (e >= 0 && e < LSEQ)
                    v = *((const float4*)(Er + (size_t)e * 64 + 4 * c4));
                split72(sm + OEH, sm + OEL, j, c4, v);
            }
            __syncthreads();

#pragma unroll 1
            for (int nt = 0; nt < 12; nt++) {
                float racc[2][4] = {{0.f, 0.f, 0.f, 0.f}, {0.f, 0.f, 0.f, 0.f}};
                const uint32_t nb = (uint32_t)((96 * wn + 8 * nt) * 144) + browB + bcolB;
#pragma unroll
                for (int ks = 0; ks < 4; ks++) {
                    uint32_t BH[2], BL[2];
                    ldmB(BH, sb + OEH + nb + ks * 32);
                    ldmB(BL, sb + OEL + nb + ks * 32);
#pragma unroll
                    for (int mt = 0; mt < 2; mt++) {
                        mmabf(racc[mt], AH[mt][ks], BH);
                        mmabf(racc[mt], AH[mt][ks], BL);
                        mmabf(racc[mt], AL[mt][ks], BH);
                    }
                }
#pragma unroll
                for (int mt = 0; mt < 2; mt++) {
                    int q = 32 * wm + 16 * mt + (lane >> 2);
                    int c = 96 * wn + 8 * nt + 2 * (lane & 3);
                    *((float2*)(Rs + q * RSP + c)) = make_float2(racc[mt][0], racc[mt][1]);
                    *((float2*)(Rs + (q + 8) * RSP + c)) = make_float2(racc[mt][2], racc[mt][3]);
                }
            }

            float sacc[2][4][4];
#pragma unroll
            for (int mt = 0; mt < 2; mt++)
#pragma unroll
                for (int nt = 0; nt < 4; nt++)
#pragma unroll
                    for (int r = 0; r < 4; r++) sacc[mt][nt][r] = 0.f;
#pragma unroll
            for (int nt = 0; nt < 4; nt++) {
                const uint32_t nb = (uint32_t)((64 * kh + 32 * wn + 8 * nt) * 144) + browB + bcolB;
#pragma unroll
                for (int ks = 0; ks < 4; ks++) {
                    uint32_t BH[2], BL[2];
                    ldmB(BH, sb + OKH + nb + ks * 32);
                    ldmB(BL, sb + OKL + nb + ks * 32);
#pragma unroll
                    for (int mt = 0; mt < 2; mt++) {
                        mmabf(sacc[mt][nt], AH[mt][ks], BH);
                        mmabf(sacc[mt][nt], AH[mt][ks], BL);
                        mmabf(sacc[mt][nt], AL[mt][ks], BH);
                    }
                }
            }
            __syncthreads();

            const bool diag = (kt == qt);
#pragma unroll
            for (int mt = 0; mt < 2; mt++) {
#pragma unroll
                for (int nt = 0; nt < 4; nt++) {
                    int kloc = 32 * wn + 8 * nt + 2 * (lane & 3);
                    int kg = k0 + 64 * kh + kloc;
#pragma unroll
                    for (int rh = 0; rh < 2; rh++) {
                        int q = 32 * wm + 16 * mt + 8 * rh + (lane >> 2);
                        int qg = q0 + q;
                        const float* rr = Rs + q * RSP + q - kloc + 63;
                        float s0 = (sacc[mt][nt][2 * rh] + rr[0]) * 0.125f;
                        float s1 = (sacc[mt][nt][2 * rh + 1] + rr[-1]) * 0.125f;
                        float p0 = __expf(s0), p1 = __expf(s1);
                        if (diag) {
                            if (kg > qg) p0 = 0.f;
                            if (kg + 1 > qg) p1 = 0.f;
                        }
                        zacc[mt][rh] += p0 + p1;
                        *((float2*)(attng + (size_t)qg * LSEQ + kg)) = make_float2(p0, p1);
                    }
                }
            }
            __syncthreads();
        }
    }

#pragma unroll
    for (int mt = 0; mt < 2; mt++)
#pragma unroll
        for (int rh = 0; rh < 2; rh++) {
            float v = zacc[mt][rh];
            v += __shfl_xor_sync(0xffffffffu, v, 1);
            v += __shfl_xor_sync(0xffffffffu, v, 2);
            zacc[mt][rh] = v;
        }
    __syncthreads();
    float* zb = Rs;
    if ((lane & 3) == 0) {
#pragma unroll
        for (int mt = 0; mt < 2; mt++)
#pragma unroll
            for (int rh = 0; rh < 2; rh++) {
                int row = 32 * wm + 16 * mt + 8 * rh + (lane >> 2);
                zb[row * 2 + wn] = zacc[mt][rh];
            }
    }
    __syncthreads();
    if (t < 128)
        g_IZ[bh * LSEQ + q0 + t] = 1.f / (zb[2 * t] + zb[2 * t + 1]);
}

// ================= Kernel B: tensor-core normalize + PV ====================
// smem: P hi [128][136bf16] | P lo | V hi [128][72bf16] | V lo | iz[128]
#define OPH 0
#define OPL 34816
#define OVH 69632
#define OVL 88064
#define OIZ 106496
#define SMEM_B_TOT 107008

__global__ void __launch_bounds__(256, 2)
pv_tc(const float* __restrict__ V, float* __restrict__ ctx, float* __restrict__ attn)
{
    extern __shared__ char sm[];
    const uint32_t sb = smem_u32(sm);
    float* smIZ = (float*)(sm + OIZ);
    if (ctx == nullptr) ctx = g_ctx_scratch;

    const int qt = 15 - (int)blockIdx.x;
    const int bh = blockIdx.y;
    const int q0 = qt * 128;
    const int t = threadIdx.x;
    const int wid = t >> 5, lane = t & 31;
    const int wm = wid >> 1, wn = wid & 1;

    const float* Vg = V + (size_t)bh * LSEQ * 64;
    float* attng = attn + (size_t)bh * LSEQ * LSEQ;
    float* ctxg = ctx + (size_t)bh * LSEQ * 64;

    if (t < 128) smIZ[t] = g_IZ[bh * LSEQ + q0 + t];
    __syncthreads();

    float cacc[2][4][4];
#pragma unroll
    for (int mt = 0; mt < 2; mt++)
#pragma unroll
        for (int nt = 0; nt < 4; nt++)
#pragma unroll
            for (int r = 0; r < 4; r++) cacc[mt][nt][r] = 0.f;

    const int arow = (lane & 7) + 8 * ((lane >> 3) & 1);
    const int acolB = 16 * (lane >> 4);
    const int btrow = (lane & 15) * 144;           // trans B: lane -> k row
    const int bncol = (32 * wn) * 2;               // n base byte (nt adds 16)

    for (int kt = 0; kt <= qt; kt++) {
        const int k0 = kt * 128;
        __syncthreads();
        for (int i = t; i < 2048; i += 256) {      // V tile [k][64], split
            int r = i >> 4, c4 = i & 15;
            split72(sm + OVH, sm + OVL, r, c4,
                    *((const float4*)(Vg + (size_t)(k0 + r) * 64 + 4 * c4)));
        }
        for (int i = t; i < 4096; i += 256) {      // P tile: normalize + split
            int r = i >> 5, c4 = i & 31;
            size_t gi = (size_t)(q0 + r) * LSEQ + k0 + 4 * c4;
            float4 pv = *((const float4*)(attng + gi));
            float iz = smIZ[r];
            pv.x *= iz; pv.y *= iz; pv.z *= iz; pv.w *= iz;
            *((float4*)(attng + gi)) = pv;
            split136(sm + OPH, sm + OPL, r, c4, pv);
        }
        __syncthreads();

#pragma unroll 2
        for (int ks = 0; ks < 8; ks++) {
            uint32_t PH[2][4], PL[2][4];
#pragma unroll
            for (int mt = 0; mt < 2; mt++) {
                uint32_t ro = (uint32_t)((32 * wm + 16 * mt + arow) * 272 + ks * 32 + acolB);
                ldmA(PH[mt], sb + OPH + ro);
                ldmA(PL[mt], sb + OPL + ro);
            }
#pragma unroll
            for (int nt = 0; nt < 4; nt++) {
                uint32_t BH[2], BL[2];
                uint32_t bo = (uint32_t)(16 * ks * 144) + btrow + bncol + nt * 16;
                ldmBT(BH, sb + OVH + bo);
                ldmBT(BL, sb + OVL + bo);
#pragma unroll
                for (int mt = 0; mt < 2; mt++) {
                    mmabf(cacc[mt][nt], PH[mt], BH);
                    mmabf(cacc[mt][nt], PH[mt], BL);
                    mmabf(cacc[mt][nt], PL[mt], BH);
                }
            }
        }
    }

    // zero-fill future columns
    const int kend = (qt + 1) * 128;
    const int nz = (LSEQ - kend) >> 2;
    if (nz > 0) {
        const float4 z4 = make_float4(0.f, 0.f, 0.f, 0.f);
        for (int i = t; i < 128 * nz; i += 256) {
            int r = i / nz, c = i - r * nz;
            *((float4*)(attng + (size_t)(q0 + r) * LSEQ + kend + 4 * c)) = z4;
        }
    }

    // ctx epilogue
#pragma unroll
    for (int mt = 0; mt < 2; mt++)
#pragma unroll
        for (int nt = 0; nt < 4; nt++)
#pragma unroll
            for (int rh = 0; rh < 2; rh++) {
                int q = q0 + 32 * wm + 16 * mt + 8 * rh + (lane >> 2);
                int d = 32 * wn + 8 * nt + 2 * (lane & 3);
                *((float2*)(ctxg + (size_t)q * 64 + d)) =
                    make_float2(cacc[mt][nt][2 * rh], cacc[mt][nt][2 * rh + 1]);
            }
}

extern "C" void kernel_launch(void* const* d_in, const int* in_sizes, int n_in,
                              void* d_out, int out_size) {
    const float* Q  = (const float*)d_in[0];
    const float* K  = (const float*)d_in[1];
    const float* V  = (const float*)d_in[2];
    const float* Er = (const float*)d_in[4];

    const long long CTXN = (long long)2 * 16 * 2048 * 64;
    const long long ATTN = (long long)2 * 16 * 2048 * 2048;
    float* out = (float*)d_out;
    float* ctx; float* attn;
    if ((long long)out_size >= CTXN + ATTN) { ctx = out; attn = out + CTXN; }
    else if ((long long)out_size == ATTN)   { ctx = nullptr; attn = out; }
    else                                    { ctx = out; attn = out; }

    cudaFuncSetAttribute(score_mma, cudaFuncAttributeMaxDynamicSharedMemorySize, SMEM_TOT);
    score_mma<<<dim3(16, 32), 256, SMEM_TOT>>>(Q, K, Er, attn);

    cudaFuncSetAttribute(pv_tc, cudaFuncAttributeMaxDynamicSharedMemorySize, SMEM_B_TOT);
    pv_tc<<<dim3(16, 32), 256, SMEM_B_TOT>>>(V, ctx, attn);
}

// round 8
// speedup vs baseline: 1.6352x; 1.6352x over previous
#include <cuda_runtime.h>
#include <cuda_bf16.h>
#include <cstdint>

#define LSEQ 2048
typedef unsigned long long ull;

__device__ float g_IZ[32 * LSEQ];
__device__ float g_ctx_scratch[2 * 16 * 2048 * 64];

// ---- smem byte offsets for score kernel (pitch 72 bf16 = 144B rows) ----
#define OQH 0
#define OQL 18432
#define OKH 36864
#define OKL 55296
#define OEH 73728
#define OEL 101376
#define ORS 129024
#define RSP 196
#define SMEM_TOT (229376)

__device__ __forceinline__ uint32_t smem_u32(const void* p) {
    uint32_t a;
    asm("{ .reg .u64 t; cvta.to.shared.u64 t, %1; cvt.u32.u64 %0, t; }" : "=r"(a) : "l"(p));
    return a;
}
__device__ __forceinline__ void ldmA(uint32_t* a, uint32_t addr) {
    asm volatile("ldmatrix.sync.aligned.m8n8.x4.shared.b16 {%0,%1,%2,%3}, [%4];"
        : "=r"(a[0]), "=r"(a[1]), "=r"(a[2]), "=r"(a[3]) : "r"(addr));
}
__device__ __forceinline__ void ldmB(uint32_t* b, uint32_t addr) {
    asm volatile("ldmatrix.sync.aligned.m8n8.x2.shared.b16 {%0,%1}, [%2];"
        : "=r"(b[0]), "=r"(b[1]) : "r"(addr));
}
__device__ __forceinline__ void ldmBT(uint32_t* b, uint32_t addr) {
    asm volatile("ldmatrix.sync.aligned.m8n8.x2.trans.shared.b16 {%0,%1}, [%2];"
        : "=r"(b[0]), "=r"(b[1]) : "r"(addr));
}
__device__ __forceinline__ void mmabf(float* d, const uint32_t* a, const uint32_t* b) {
    asm volatile("mma.sync.aligned.m16n8k16.row.col.f32.bf16.bf16.f32 "
        "{%0,%1,%2,%3}, {%4,%5,%6,%7}, {%8,%9}, {%0,%1,%2,%3};"
        : "+f"(d[0]), "+f"(d[1]), "+f"(d[2]), "+f"(d[3])
        : "r"(a[0]), "r"(a[1]), "r"(a[2]), "r"(a[3]), "r"(b[0]), "r"(b[1]));
}
__device__ __forceinline__ uint32_t pkbf(float a, float b) {
    __nv_bfloat162 h = __floats2bfloat162_rn(a, b);
    return *(uint32_t*)&h;
}
__device__ __forceinline__ void split72(char* hi, char* lo, int r, int c4, float4 v) {
    float hx = __bfloat162float(__float2bfloat16(v.x));
    float hy = __bfloat162float(__float2bfloat16(v.y));
    float hz = __bfloat162float(__float2bfloat16(v.z));
    float hw = __bfloat162float(__float2bfloat16(v.w));
    int off = r * 144 + c4 * 8;
    *(uint2*)(hi + off) = make_uint2(pkbf(v.x, v.y), pkbf(v.z, v.w));
    *(uint2*)(lo + off) = make_uint2(pkbf(v.x - hx, v.y - hy), pkbf(v.z - hz, v.w - hw));
}
__device__ __forceinline__ void split136(char* hi, char* lo, int r, int c4, float4 v) {
    float hx = __bfloat162float(__float2bfloat16(v.x));
    float hy = __bfloat162float(__float2bfloat16(v.y));
    float hz = __bfloat162float(__float2bfloat16(v.z));
    float hw = __bfloat162float(__float2bfloat16(v.w));
    int off = r * 272 + c4 * 8;
    *(uint2*)(hi + off) = make_uint2(pkbf(v.x, v.y), pkbf(v.z, v.w));
    *(uint2*)(lo + off) = make_uint2(pkbf(v.x - hx, v.y - hy), pkbf(v.z - hz, v.w - hw));
}

// ================= Kernel A: mma.sync scores (R6 winner, unchanged) ========
__global__ void __launch_bounds__(256, 1)
score_mma(const float* __restrict__ Q, const float* __restrict__ K,
          const float* __restrict__ Er, float* __restrict__ attn)
{
    extern __shared__ char sm[];
    const uint32_t sb = smem_u32(sm);
    float* Rs = (float*)(sm + ORS);

    const int qt = 15 - (int)blockIdx.x;
    const int bh = blockIdx.y;
    const int q0 = qt * 128;
    const int t = threadIdx.x;
    const int wid = t >> 5, lane = t & 31;
    const int wm = wid >> 1, wn = wid & 1;

    const float* Qg = Q + (size_t)bh * LSEQ * 64;
    const float* Kg = K + (size_t)bh * LSEQ * 64;
    float* attng = attn + (size_t)bh * LSEQ * LSEQ;

    for (int i = t; i < 2048; i += 256) {
        int r = i >> 4, c4 = i & 15;
        split72(sm + OQH, sm + OQL, r, c4,
                *((const float4*)(Qg + (size_t)(q0 + r) * 64 + 4 * c4)));
    }
    __syncthreads();

    const int arow = (lane & 7) + 8 * ((lane >> 3) & 1);
    const int acolB = 16 * (lane >> 4);
    uint32_t AH[2][4][4], AL[2][4][4];
#pragma unroll
    for (int mt = 0; mt < 2; mt++)
#pragma unroll
        for (int ks = 0; ks < 4; ks++) {
            uint32_t ro = (uint32_t)((32 * wm + 16 * mt + arow) * 144 + ks * 32 + acolB);
            ldmA(AH[mt][ks], sb + OQH + ro);
            ldmA(AL[mt][ks], sb + OQL + ro);
        }

    const int browB = (lane & 7) * 144;
    const int bcolB = 16 * ((lane >> 3) & 1);
    float zacc[2][2] = {{0.f, 0.f}, {0.f, 0.f}};

    for (int kt = 0; kt <= qt; kt++) {
        const int k0 = kt * 128;
        __syncthreads();
        for (int i = t; i < 2048; i += 256) {
            int r = i >> 4, c4 = i & 15;
            split72(sm + OKH, sm + OKL, r, c4,
                    *((const float4*)(Kg + (size_t)(k0 + r) * 64 + 4 * c4)));
        }
#pragma unroll 1
        for (int kh = 0; kh < 2; kh++) {
            const int vlo = q0 - k0 - 64 * kh - 63;
            for (int i = t; i < 3072; i += 256) {
                int j = i >> 4, c4 = i & 15;
                int e = 2047 - (vlo + j);
                float4 v = make_float4(0.f, 0.f, 0.f, 0.f);
                if (e >= 0 && e < LSEQ)
                    v = *((const float4*)(Er + (size_t)e * 64 + 4 * c4));
                split72(sm + OEH, sm + OEL, j, c4, v);
            }
            __syncthreads();

#pragma unroll 1
            for (int nt = 0; nt < 12; nt++) {
                float racc[2][4] = {{0.f, 0.f, 0.f, 0.f}, {0.f, 0.f, 0.f, 0.f}};
                const uint32_t nb = (uint32_t)((96 * wn + 8 * nt) * 144) + browB + bcolB;
#pragma unroll
                for (int ks = 0; ks < 4; ks++) {
                    uint32_t BH[2], BL[2];
                    ldmB(BH, sb + OEH + nb + ks * 32);
                    ldmB(BL, sb + OEL + nb + ks * 32);
#pragma unroll
                    for (int mt = 0; mt < 2; mt++) {
                        mmabf(racc[mt], AH[mt][ks], BH);
                        mmabf(racc[mt], AH[mt][ks], BL);
                        mmabf(racc[mt], AL[mt][ks], BH);
                    }
                }
#pragma unroll
                for (int mt = 0; mt < 2; mt++) {
                    int q = 32 * wm + 16 * mt + (lane >> 2);
                    int c = 96 * wn + 8 * nt + 2 * (lane & 3);
                    *((float2*)(Rs + q * RSP + c)) = make_float2(racc[mt][0], racc[mt][1]);
                    *((float2*)(Rs + (q + 8) * RSP + c)) = make_float2(racc[mt][2], racc[mt][3]);
                }
            }

            float sacc[2][4][4];
#pragma unroll
            for (int mt = 0; mt < 2; mt++)
#pragma unroll
                for (int nt = 0; nt < 4; nt++)
#pragma unroll
                    for (int r = 0; r < 4; r++) sacc[mt][nt][r] = 0.f;
#pragma unroll
            for (int nt = 0; nt < 4; nt++) {
                const uint32_t nb = (uint32_t)((64 * kh + 32 * wn + 8 * nt) * 144) + browB + bcolB;
#pragma unroll
                for (int ks = 0; ks < 4; ks++) {
                    uint32_t BH[2], BL[2];
                    ldmB(BH, sb + OKH + nb + ks * 32);
                    ldmB(BL, sb + OKL + nb + ks * 32);
#pragma unroll
                    for (int mt = 0; mt < 2; mt++) {
                        mmabf(sacc[mt][nt], AH[mt][ks], BH);
                        mmabf(sacc[mt][nt], AH[mt][ks], BL);
                        mmabf(sacc[mt][nt], AL[mt][ks], BH);
                    }
                }
            }
            __syncthreads();

            const bool diag = (kt == qt);
#pragma unroll
            for (int mt = 0; mt < 2; mt++) {
#pragma unroll
                for (int nt = 0; nt < 4; nt++) {
                    int kloc = 32 * wn + 8 * nt + 2 * (lane & 3);
                    int kg = k0 + 64 * kh + kloc;
#pragma unroll
                    for (int rh = 0; rh < 2; rh++) {
                        int q = 32 * wm + 16 * mt + 8 * rh + (lane >> 2);
                        int qg = q0 + q;
                        const float* rr = Rs + q * RSP + q - kloc + 63;
                        float s0 = (sacc[mt][nt][2 * rh] + rr[0]) * 0.125f;
                        float s1 = (sacc[mt][nt][2 * rh + 1] + rr[-1]) * 0.125f;
                        float p0 = __expf(s0), p1 = __expf(s1);
                        if (diag) {
                            if (kg > qg) p0 = 0.f;
                            if (kg + 1 > qg) p1 = 0.f;
                        }
                        zacc[mt][rh] += p0 + p1;
                        *((float2*)(attng + (size_t)qg * LSEQ + kg)) = make_float2(p0, p1);
                    }
                }
            }
            __syncthreads();
        }
    }

#pragma unroll
    for (int mt = 0; mt < 2; mt++)
#pragma unroll
        for (int rh = 0; rh < 2; rh++) {
            float v = zacc[mt][rh];
            v += __shfl_xor_sync(0xffffffffu, v, 1);
            v += __shfl_xor_sync(0xffffffffu, v, 2);
            zacc[mt][rh] = v;
        }
    __syncthreads();
    float* zb = Rs;
    if ((lane & 3) == 0) {
#pragma unroll
        for (int mt = 0; mt < 2; mt++)
#pragma unroll
            for (int rh = 0; rh < 2; rh++) {
                int row = 32 * wm + 16 * mt + 8 * rh + (lane >> 2);
                zb[row * 2 + wn] = zacc[mt][rh];
            }
    }
    __syncthreads();
    if (t < 128)
        g_IZ[bh * LSEQ + q0 + t] = 1.f / (zb[2 * t] + zb[2 * t + 1]);
}

// ================= Kernel B: TC PV with batched (high-MLP) loads ===========
#define OPH 0
#define OPL 34816
#define OVH 69632
#define OVL 88064
#define OIZ 106496
#define SMEM_B_TOT 107008

__global__ void __launch_bounds__(256, 2)
pv_tc(const float* __restrict__ V, float* __restrict__ ctx, float* __restrict__ attn)
{
    extern __shared__ char sm[];
    const uint32_t sb = smem_u32(sm);
    float* smIZ = (float*)(sm + OIZ);
    if (ctx == nullptr) ctx = g_ctx_scratch;

    const int qt = 15 - (int)blockIdx.x;
    const int bh = blockIdx.y;
    const int q0 = qt * 128;
    const int t = threadIdx.x;
    const int wid = t >> 5, lane = t & 31;
    const int wm = wid >> 1, wn = wid & 1;

    const float* Vg = V + (size_t)bh * LSEQ * 64;
    float* attng = attn + (size_t)bh * LSEQ * LSEQ;
    float* ctxg = ctx + (size_t)bh * LSEQ * 64;

    if (t < 128) smIZ[t] = g_IZ[bh * LSEQ + q0 + t];
    __syncthreads();

    float cacc[2][4][4];
#pragma unroll
    for (int mt = 0; mt < 2; mt++)
#pragma unroll
        for (int nt = 0; nt < 4; nt++)
#pragma unroll
            for (int r = 0; r < 4; r++) cacc[mt][nt][r] = 0.f;

    const int arow = (lane & 7) + 8 * ((lane >> 3) & 1);
    const int acolB = 16 * (lane >> 4);
    const int btrow = (lane & 15) * 144;
    const int bncol = (32 * wn) * 2;

    // precomputed per-thread indices for batched phases
    const int vr = t >> 4, vc4 = t & 15;               // V: rows vr+8*jj
    const int pr = t >> 5, pc4 = t & 31;               // P: rows pr+8*jj

    for (int kt = 0; kt <= qt; kt++) {
        const int k0 = kt * 128;
        __syncthreads();

        // ---- V tile: batch 8 LDG.128, then convert ----
        float4 vbuf[8];
#pragma unroll
        for (int jj = 0; jj < 8; jj++)
            vbuf[jj] = *((const float4*)(Vg + (size_t)(k0 + vr + 16 * jj) * 64 + 4 * vc4));
#pragma unroll
        for (int jj = 0; jj < 8; jj++)
            split72(sm + OVH, sm + OVL, vr + 16 * jj, vc4, vbuf[jj]);

        // ---- P tile: two halves, each batch 8 LDG.128 then process ----
#pragma unroll 1
        for (int half = 0; half < 2; half++) {
            const int rbase = 64 * half + pr;
            float4 pbuf[8];
#pragma unroll
            for (int jj = 0; jj < 8; jj++)
                pbuf[jj] = *((const float4*)(attng +
                    (size_t)(q0 + rbase + 8 * jj) * LSEQ + k0 + 4 * pc4));
#pragma unroll
            for (int jj = 0; jj < 8; jj++) {
                int r = rbase + 8 * jj;
                float iz = smIZ[r];
                float4 pv = pbuf[jj];
                pv.x *= iz; pv.y *= iz; pv.z *= iz; pv.w *= iz;
                *((float4*)(attng + (size_t)(q0 + r) * LSEQ + k0 + 4 * pc4)) = pv;
                split136(sm + OPH, sm + OPL, r, pc4, pv);
            }
        }
        __syncthreads();

#pragma unroll 2
        for (int ks = 0; ks < 8; ks++) {
            uint32_t PH[2][4], PL[2][4];
#pragma unroll
            for (int mt = 0; mt < 2; mt++) {
                uint32_t ro = (uint32_t)((32 * wm + 16 * mt + arow) * 272 + ks * 32 + acolB);
                ldmA(PH[mt], sb + OPH + ro);
                ldmA(PL[mt], sb + OPL + ro);
            }
#pragma unroll
            for (int nt = 0; nt < 4; nt++) {
                uint32_t BH[2], BL[2];
                uint32_t bo = (uint32_t)(16 * ks * 144) + btrow + bncol + nt * 16;
                ldmBT(BH, sb + OVH + bo);
                ldmBT(BL, sb + OVL + bo);
#pragma unroll
                for (int mt = 0; mt < 2; mt++) {
                    mmabf(cacc[mt][nt], PH[mt], BH);
                    mmabf(cacc[mt][nt], PH[mt], BL);
                    mmabf(cacc[mt][nt], PL[mt], BH);
                }
            }
        }
    }

    // zero-fill future columns
    const int kend = (qt + 1) * 128;
    const int nz = (LSEQ - kend) >> 2;
    if (nz > 0) {
        const float4 z4 = make_float4(0.f, 0.f, 0.f, 0.f);
        for (int i = t; i < 128 * nz; i += 256) {
            int r = i / nz, c = i - r * nz;
            *((float4*)(attng + (size_t)(q0 + r) * LSEQ + kend + 4 * c)) = z4;
        }
    }

    // ctx epilogue
#pragma unroll
    for (int mt = 0; mt < 2; mt++)
#pragma unroll
        for (int nt = 0; nt < 4; nt++)
#pragma unroll
            for (int rh = 0; rh < 2; rh++) {
                int q = q0 + 32 * wm + 16 * mt + 8 * rh + (lane >> 2);
                int d = 32 * wn + 8 * nt + 2 * (lane & 3);
                *((float2*)(ctxg + (size_t)q * 64 + d)) =
                    make_float2(cacc[mt][nt][2 * rh], cacc[mt][nt][2 * rh + 1]);
            }
}

extern "C" void kernel_launch(void* const* d_in, const int* in_sizes, int n_in,
                              void* d_out, int out_size) {
    const float* Q  = (const float*)d_in[0];
    const float* K  = (const float*)d_in[1];
    const float* V  = (const float*)d_in[2];
    const float* Er = (const float*)d_in[4];

    const long long CTXN = (long long)2 * 16 * 2048 * 64;
    const long long ATTN = (long long)2 * 16 * 2048 * 2048;
    float* out = (float*)d_out;
    float* ctx; float* attn;
    if ((long long)out_size >= CTXN + ATTN) { ctx = out; attn = out + CTXN; }
    else if ((long long)out_size == ATTN)   { ctx = nullptr; attn = out; }
    else                                    { ctx = out; attn = out; }

    cudaFuncSetAttribute(score_mma, cudaFuncAttributeMaxDynamicSharedMemorySize, SMEM_TOT);
    score_mma<<<dim3(16, 32), 256, SMEM_TOT>>>(Q, K, Er, attn);

    cudaFuncSetAttribute(pv_tc, cudaFuncAttributeMaxDynamicSharedMemorySize, SMEM_B_TOT);
    pv_tc<<<dim3(16, 32), 256, SMEM_B_TOT>>>(V, ctx, attn);
}

// round 9
// speedup vs baseline: 2.3173x; 1.4171x over previous
#include <cuda_runtime.h>
#include <cuda_bf16.h>
#include <cstdint>

#define LSEQ 2048
typedef unsigned long long ull;

__device__ float g_IZ[32 * LSEQ];
__device__ float g_ctx_scratch[2 * 16 * 2048 * 64];

// ---- score kernel smem (operand pitch 72 bf16 = 144B rows) ----
#define OKH 0
#define OKL 18432
#define OEH 36864
#define OEL 55296
#define ORS 73728
#define RSPITCH 260
#define SMEM_TOT (73728 + 128 * RSPITCH * 4)   // 206848

__device__ __forceinline__ uint32_t smem_u32(const void* p) {
    uint32_t a;
    asm("{ .reg .u64 t; cvta.to.shared.u64 t, %1; cvt.u32.u64 %0, t; }" : "=r"(a) : "l"(p));
    return a;
}
__device__ __forceinline__ void ldmA(uint32_t* a, uint32_t addr) {
    asm volatile("ldmatrix.sync.aligned.m8n8.x4.shared.b16 {%0,%1,%2,%3}, [%4];"
        : "=r"(a[0]), "=r"(a[1]), "=r"(a[2]), "=r"(a[3]) : "r"(addr));
}
__device__ __forceinline__ void ldmB(uint32_t* b, uint32_t addr) {
    asm volatile("ldmatrix.sync.aligned.m8n8.x2.shared.b16 {%0,%1}, [%2];"
        : "=r"(b[0]), "=r"(b[1]) : "r"(addr));
}
__device__ __forceinline__ void ldmBT(uint32_t* b, uint32_t addr) {
    asm volatile("ldmatrix.sync.aligned.m8n8.x2.trans.shared.b16 {%0,%1}, [%2];"
        : "=r"(b[0]), "=r"(b[1]) : "r"(addr));
}
__device__ __forceinline__ void mmabf(float* d, const uint32_t* a, const uint32_t* b) {
    asm volatile("mma.sync.aligned.m16n8k16.row.col.f32.bf16.bf16.f32 "
        "{%0,%1,%2,%3}, {%4,%5,%6,%7}, {%8,%9}, {%0,%1,%2,%3};"
        : "+f"(d[0]), "+f"(d[1]), "+f"(d[2]), "+f"(d[3])
        : "r"(a[0]), "r"(a[1]), "r"(a[2]), "r"(a[3]), "r"(b[0]), "r"(b[1]));
}
__device__ __forceinline__ uint32_t pkbf(float a, float b) {
    __nv_bfloat162 h = __floats2bfloat162_rn(a, b);
    return *(uint32_t*)&h;
}
__device__ __forceinline__ void split72(char* hi, char* lo, int r, int c4, float4 v) {
    float hx = __bfloat162float(__float2bfloat16(v.x));
    float hy = __bfloat162float(__float2bfloat16(v.y));
    float hz = __bfloat162float(__float2bfloat16(v.z));
    float hw = __bfloat162float(__float2bfloat16(v.w));
    int off = r * 144 + c4 * 8;
    *(uint2*)(hi + off) = make_uint2(pkbf(v.x, v.y), pkbf(v.z, v.w));
    *(uint2*)(lo + off) = make_uint2(pkbf(v.x - hx, v.y - hy), pkbf(v.z - hz, v.w - hw));
}
__device__ __forceinline__ void split136(char* hi, char* lo, int r, int c4, float4 v) {
    float hx = __bfloat162float(__float2bfloat16(v.x));
    float hy = __bfloat162float(__float2bfloat16(v.y));
    float hz = __bfloat162float(__float2bfloat16(v.z));
    float hw = __bfloat162float(__float2bfloat16(v.w));
    int off = r * 272 + c4 * 8;
    *(uint2*)(hi + off) = make_uint2(pkbf(v.x, v.y), pkbf(v.z, v.w));
    *(uint2*)(lo + off) = make_uint2(pkbf(v.x - hx, v.y - hy), pkbf(v.z - hz, v.w - hw));
}

// ========== Kernel A: scores with incremental R ring ==========
__global__ void __launch_bounds__(256, 1)
score_mma(const float* __restrict__ Q, const float* __restrict__ K,
          const float* __restrict__ Er, float* __restrict__ attn)
{
    extern __shared__ char sm[];
    const uint32_t sb = smem_u32(sm);
    float* Rs = (float*)(sm + ORS);

    const int qt = 15 - (int)blockIdx.x;
    const int bh = blockIdx.y;
    const int q0 = qt * 128;
    const int t = threadIdx.x;
    const int wid = t >> 5, lane = t & 31;
    const int wm = wid >> 1, wn = wid & 1;

    const float* Qg = Q + (size_t)bh * LSEQ * 64;
    const float* Kg = K + (size_t)bh * LSEQ * 64;
    float* attng = attn + (size_t)bh * LSEQ * LSEQ;

    // ---- stage Q in ring region (reused after fragments are in regs) ----
    {
        const int r = t >> 1, c8 = t & 1;   // 2 float4 per thread
#pragma unroll
        for (int jj = 0; jj < 1; jj++) { }
    }
    for (int i = t; i < 2048; i += 256) {
        int r = i >> 4, c4 = i & 15;
        split72(sm + ORS, sm + ORS + 18432, r, c4,
                *((const float4*)(Qg + (size_t)(q0 + r) * 64 + 4 * c4)));
    }
    __syncthreads();

    const int arow = (lane & 7) + 8 * ((lane >> 3) & 1);
    const int acolB = 16 * (lane >> 4);
    uint32_t AH[2][4][4], AL[2][4][4];
#pragma unroll
    for (int mt = 0; mt < 2; mt++)
#pragma unroll
        for (int ks = 0; ks < 4; ks++) {
            uint32_t ro = (uint32_t)((32 * wm + 16 * mt + arow) * 144 + ks * 32 + acolB);
            ldmA(AH[mt][ks], sb + ORS + ro);
            ldmA(AL[mt][ks], sb + ORS + 18432 + ro);
        }

    const int browB = (lane & 7) * 144;
    const int bcolB = 16 * ((lane >> 3) & 1);
    float zacc[2][2] = {{0.f, 0.f}, {0.f, 0.f}};

    const int lr = t >> 4, lc4 = t & 15;     // load indices: 8 rows each, stride 16

    for (int h = 0; h <= qt; h++) {
        const int k0 = (qt - h) * 128;
        __syncthreads();     // ring write-slot + K/E free

        // ---- batched K tile load + split ----
        float4 kb[8];
#pragma unroll
        for (int jj = 0; jj < 8; jj++)
            kb[jj] = *((const float4*)(Kg + (size_t)(k0 + lr + 16 * jj) * 64 + 4 * lc4));
#pragma unroll
        for (int jj = 0; jj < 8; jj++)
            split72(sm + OKH, sm + OKL, lr + 16 * jj, lc4, kb[jj]);

        // ---- batched E~ block load + split: row j -> Er[2047 - 128h - j] ----
        const int ebase = 2047 - 128 * h;
        float4 eb[8];
#pragma unroll
        for (int jj = 0; jj < 8; jj++)
            eb[jj] = *((const float4*)(Er + (size_t)(ebase - (lr + 16 * jj)) * 64 + 4 * lc4));
#pragma unroll
        for (int jj = 0; jj < 8; jj++)
            split72(sm + OEH, sm + OEL, lr + 16 * jj, lc4, eb[jj]);
        __syncthreads();

        // ---- R phase: 128 new cols (block D_{h+1}) -> ring slot (h+1)&1 ----
        const int slotW = 128 * ((h + 1) & 1);
#pragma unroll 1
        for (int nt = 0; nt < 8; nt++) {
            float racc[2][4] = {{0.f, 0.f, 0.f, 0.f}, {0.f, 0.f, 0.f, 0.f}};
            const uint32_t nb = (uint32_t)((64 * wn + 8 * nt) * 144) + browB + bcolB;
#pragma unroll
            for (int ks = 0; ks < 4; ks++) {
                uint32_t BH[2], BL[2];
                ldmB(BH, sb + OEH + nb + ks * 32);
                ldmB(BL, sb + OEL + nb + ks * 32);
#pragma unroll
                for (int mt = 0; mt < 2; mt++) {
                    mmabf(racc[mt], AH[mt][ks], BH);
                    mmabf(racc[mt], AH[mt][ks], BL);
                    mmabf(racc[mt], AL[mt][ks], BH);
                }
            }
            const int c = slotW + 64 * wn + 8 * nt + 2 * (lane & 3);
#pragma unroll
            for (int mt = 0; mt < 2; mt++) {
                int q = 32 * wm + 16 * mt + (lane >> 2);
                *((float2*)(Rs + q * RSPITCH + c)) = make_float2(racc[mt][0], racc[mt][1]);
                *((float2*)(Rs + (q + 8) * RSPITCH + c)) = make_float2(racc[mt][2], racc[mt][3]);
            }
        }
        __syncthreads();     // ring visible

        // ---- S + epilogue over two 64-col halves (no smem writes here) ----
        const int sA = 128 * ((h + 1) & 1);   // d >= 0 -> D_{h+1}
        const int sB = 128 * (h & 1);         // d <  0 -> D_h
        const bool diag = (h == 0);
#pragma unroll 1
        for (int kh = 0; kh < 2; kh++) {
            float sacc[2][4][4];
#pragma unroll
            for (int mt = 0; mt < 2; mt++)
#pragma unroll
                for (int nt = 0; nt < 4; nt++)
#pragma unroll
                    for (int r = 0; r < 4; r++) sacc[mt][nt][r] = 0.f;
#pragma unroll
            for (int nt = 0; nt < 4; nt++) {
                const uint32_t nb = (uint32_t)((64 * kh + 32 * wn + 8 * nt) * 144) + browB + bcolB;
#pragma unroll
                for (int ks = 0; ks < 4; ks++) {
                    uint32_t BH[2], BL[2];
                    ldmB(BH, sb + OKH + nb + ks * 32);
                    ldmB(BL, sb + OKL + nb + ks * 32);
#pragma unroll
                    for (int mt = 0; mt < 2; mt++) {
                        mmabf(sacc[mt][nt], AH[mt][ks], BH);
                        mmabf(sacc[mt][nt], AH[mt][ks], BL);
                        mmabf(sacc[mt][nt], AL[mt][ks], BH);
                    }
                }
            }
#pragma unroll
            for (int mt = 0; mt < 2; mt++) {
#pragma unroll
                for (int nt = 0; nt < 4; nt++) {
                    const int klocal = 64 * kh + 32 * wn + 8 * nt + 2 * (lane & 3);
                    const int kg = k0 + klocal;
#pragma unroll
                    for (int rh = 0; rh < 2; rh++) {
                        const int r = 32 * wm + 16 * mt + 8 * rh + (lane >> 2);
                        const int qg = q0 + r;
                        const int d0 = r - klocal;
                        const int d1 = d0 - 1;
                        float r0 = Rs[r * RSPITCH + ((d0 & 127) + (d0 >= 0 ? sA : sB))];
                        float r1 = Rs[r * RSPITCH + ((d1 & 127) + (d1 >= 0 ? sA : sB))];
                        float s0 = (sacc[mt][nt][2 * rh] + r0) * 0.125f;
                        float s1 = (sacc[mt][nt][2 * rh + 1] + r1) * 0.125f;
                        float p0 = __expf(s0), p1 = __expf(s1);
                        if (diag) {
                            if (kg > qg) p0 = 0.f;
                            if (kg + 1 > qg) p1 = 0.f;
                        }
                        zacc[mt][rh] += p0 + p1;
                        *((float2*)(attng + (size_t)qg * LSEQ + kg)) = make_float2(p0, p1);
                    }
                }
            }
        }
    }

    // ---- z reduce ----
#pragma unroll
    for (int mt = 0; mt < 2; mt++)
#pragma unroll
        for (int rh = 0; rh < 2; rh++) {
            float v = zacc[mt][rh];
            v += __shfl_xor_sync(0xffffffffu, v, 1);
            v += __shfl_xor_sync(0xffffffffu, v, 2);
            zacc[mt][rh] = v;
        }
    __syncthreads();
    float* zb = Rs;
    if ((lane & 3) == 0) {
#pragma unroll
        for (int mt = 0; mt < 2; mt++)
#pragma unroll
            for (int rh = 0; rh < 2; rh++) {
                int row = 32 * wm + 16 * mt + 8 * rh + (lane >> 2);
                zb[row * 2 + wn] = zacc[mt][rh];
            }
    }
    __syncthreads();
    if (t < 128)
        g_IZ[bh * LSEQ + q0 + t] = 1.f / (zb[2 * t] + zb[2 * t + 1]);
}

// ========== Kernel B: TC PV with batched loads (R8 winner, unchanged) ======
#define OPH 0
#define OPL 34816
#define OVH 69632
#define OVL 88064
#define OIZ 106496
#define SMEM_B_TOT 107008

__global__ void __launch_bounds__(256, 2)
pv_tc(const float* __restrict__ V, float* __restrict__ ctx, float* __restrict__ attn)
{
    extern __shared__ char sm[];
    const uint32_t sb = smem_u32(sm);
    float* smIZ = (float*)(sm + OIZ);
    if (ctx == nullptr) ctx = g_ctx_scratch;

    const int qt = 15 - (int)blockIdx.x;
    const int bh = blockIdx.y;
    const int q0 = qt * 128;
    const int t = threadIdx.x;
    const int wid = t >> 5, lane = t & 31;
    const int wm = wid >> 1, wn = wid & 1;

    const float* Vg = V + (size_t)bh * LSEQ * 64;
    float* attng = attn + (size_t)bh * LSEQ * LSEQ;
    float* ctxg = ctx + (size_t)bh * LSEQ * 64;

    if (t < 128) smIZ[t] = g_IZ[bh * LSEQ + q0 + t];
    __syncthreads();

    float cacc[2][4][4];
#pragma unroll
    for (int mt = 0; mt < 2; mt++)
#pragma unroll
        for (int nt = 0; nt < 4; nt++)
#pragma unroll
            for (int r = 0; r < 4; r++) cacc[mt][nt][r] = 0.f;

    const int arow = (lane & 7) + 8 * ((lane >> 3) & 1);
    const int acolB = 16 * (lane >> 4);
    const int btrow = (lane & 15) * 144;
    const int bncol = (32 * wn) * 2;

    const int vr = t >> 4, vc4 = t & 15;
    const int pr = t >> 5, pc4 = t & 31;

    for (int kt = 0; kt <= qt; kt++) {
        const int k0 = kt * 128;
        __syncthreads();

        float4 vbuf[8];
#pragma unroll
        for (int jj = 0; jj < 8; jj++)
            vbuf[jj] = *((const float4*)(Vg + (size_t)(k0 + vr + 16 * jj) * 64 + 4 * vc4));
#pragma unroll
        for (int jj = 0; jj < 8; jj++)
            split72(sm + OVH, sm + OVL, vr + 16 * jj, vc4, vbuf[jj]);

#pragma unroll 1
        for (int half = 0; half < 2; half++) {
            const int rbase = 64 * half + pr;
            float4 pbuf[8];
#pragma unroll
            for (int jj = 0; jj < 8; jj++)
                pbuf[jj] = *((const float4*)(attng +
                    (size_t)(q0 + rbase + 8 * jj) * LSEQ + k0 + 4 * pc4));
#pragma unroll
            for (int jj = 0; jj < 8; jj++) {
                int r = rbase + 8 * jj;
                float iz = smIZ[r];
                float4 pv = pbuf[jj];
                pv.x *= iz; pv.y *= iz; pv.z *= iz; pv.w *= iz;
                *((float4*)(attng + (size_t)(q0 + r) * LSEQ + k0 + 4 * pc4)) = pv;
                split136(sm + OPH, sm + OPL, r, pc4, pv);
            }
        }
        __syncthreads();

#pragma unroll 2
        for (int ks = 0; ks < 8; ks++) {
            uint32_t PH[2][4], PL[2][4];
#pragma unroll
            for (int mt = 0; mt < 2; mt++) {
                uint32_t ro = (uint32_t)((32 * wm + 16 * mt + arow) * 272 + ks * 32 + acolB);
                ldmA(PH[mt], sb + OPH + ro);
                ldmA(PL[mt], sb + OPL + ro);
            }
#pragma unroll
            for (int nt = 0; nt < 4; nt++) {
                uint32_t BH[2], BL[2];
                uint32_t bo = (uint32_t)(16 * ks * 144) + btrow + bncol + nt * 16;
                ldmBT(BH, sb + OVH + bo);
                ldmBT(BL, sb + OVL + bo);
#pragma unroll
                for (int mt = 0; mt < 2; mt++) {
                    mmabf(cacc[mt][nt], PH[mt], BH);
                    mmabf(cacc[mt][nt], PH[mt], BL);
                    mmabf(cacc[mt][nt], PL[mt], BH);
                }
            }
        }
    }

    const int kend = (qt + 1) * 128;
    const int nz = (LSEQ - kend) >> 2;
    if (nz > 0) {
        const float4 z4 = make_float4(0.f, 0.f, 0.f, 0.f);
        for (int i = t; i < 128 * nz; i += 256) {
            int r = i / nz, c = i - r * nz;
            *((float4*)(attng + (size_t)(q0 + r) * LSEQ + kend + 4 * c)) = z4;
        }
    }

#pragma unroll
    for (int mt = 0; mt < 2; mt++)
#pragma unroll
        for (int nt = 0; nt < 4; nt++)
#pragma unroll
            for (int rh = 0; rh < 2; rh++) {
                int q = q0 + 32 * wm + 16 * mt + 8 * rh + (lane >> 2);
                int d = 32 * wn + 8 * nt + 2 * (lane & 3);
                *((float2*)(ctxg + (size_t)q * 64 + d)) =
                    make_float2(cacc[mt][nt][2 * rh], cacc[mt][nt][2 * rh + 1]);
            }
}

extern "C" void kernel_launch(void* const* d_in, const int* in_sizes, int n_in,
                              void* d_out, int out_size) {
    const float* Q  = (const float*)d_in[0];
    const float* K  = (const float*)d_in[1];
    const float* V  = (const float*)d_in[2];
    const float* Er = (const float*)d_in[4];

    const long long CTXN = (long long)2 * 16 * 2048 * 64;
    const long long ATTN = (long long)2 * 16 * 2048 * 2048;
    float* out = (float*)d_out;
    float* ctx; float* attn;
    if ((long long)out_size >= CTXN + ATTN) { ctx = out; attn = out + CTXN; }
    else if ((long long)out_size == ATTN)   { ctx = nullptr; attn = out; }
    else                                    { ctx = out; attn = out; }

    cudaFuncSetAttribute(score_mma, cudaFuncAttributeMaxDynamicSharedMemorySize, SMEM_TOT);
    score_mma<<<dim3(16, 32), 256, SMEM_TOT>>>(Q, K, Er, attn);

    cudaFuncSetAttribute(pv_tc, cudaFuncAttributeMaxDynamicSharedMemorySize, SMEM_B_TOT);
    pv_tc<<<dim3(16, 32), 256, SMEM_B_TOT>>>(V, ctx, attn);
}